// round 15
// baseline (speedup 1.0000x reference)
#include <cuda_runtime.h>
#include <math.h>

#define KE_KCAL 332.0636f

// ---------------- scratch (no allocations allowed) ----------------
__device__ float4   g_atoms[262144];  // packed per-atom: x,y,z, (z | mol<<8)
__device__ float    g_acc[1024 * 32]; // padded per-molecule accumulators
__device__ float    g_zpd[128];       // z^z_exp / d
__device__ float    g_k[8];           // c'_k = c_k*KE/csum ; e_k
__device__ unsigned g_done;           // edges block-completion counter

// ---------------- atom packing + consts + acc zero (R8 verbatim) ----------
__global__ void __launch_bounds__(256)
k_atoms(const float* __restrict__ xyz,
        const int*   __restrict__ z,
        const int*   __restrict__ na,
        const float* __restrict__ d_inv,  const float* __restrict__ ze_inv,
        const float* __restrict__ c_inv,  const float* __restrict__ ex_inv,
        int N, int M) {
    __shared__ float s_xyz[768];      // 256 atoms * 3 floats, staged coalesced
    int t = threadIdx.x;
    int gtid = blockIdx.x * blockDim.x + t;

    // block 0: compute softplus consts + zpd table once; reset done counter
    if (blockIdx.x == 0) {
        if (t == 0)      g_done = 0u;
        if (t < 4)       g_k[t + 4] = log1pf(expf(__ldg(&ex_inv[t])));
        else if (t == 4) {
            float csum = 0.f, cc[4];
            #pragma unroll
            for (int k = 0; k < 4; k++) {
                cc[k] = log1pf(expf(__ldg(&c_inv[k])));
                csum += cc[k];
            }
            float s = KE_KCAL / csum;
            #pragma unroll
            for (int k = 0; k < 4; k++) g_k[k] = cc[k] * s;
        }
        if (t >= 32 && t < 160) {
            int zz = t - 32;
            float ze = log1pf(expf(__ldg(&ze_inv[0])));
            float dinv = 1.f / log1pf(expf(__ldg(&d_inv[0])));
            g_zpd[zz] = (zz == 0) ? 0.f : powf((float)zz, ze) * dinv;
        }
    }

    // zero accumulators
    if (gtid < 2048) {
        float4 zv = make_float4(0.f, 0.f, 0.f, 0.f);
        #pragma unroll
        for (int k = 0; k < 4; k++)
            ((float4*)g_acc)[gtid + k * 2048] = zv;
    }

    // ---- stage this block's xyz chunk through shared (coalesced float4) ----
    int blockBase = blockIdx.x * blockDim.x;
    int nAtoms = min(256, N - blockBase);
    if (nAtoms <= 0) return;
    {
        int nFloats = nAtoms * 3;
        int nVec = nFloats >> 2;
        const float4* src = (const float4*)(xyz + blockBase * 3);
        if (t < nVec) ((float4*)s_xyz)[t] = src[t];
        int rem = nFloats - nVec * 4;
        if (t < rem) s_xyz[nVec * 4 + t] = xyz[blockBase * 3 + nVec * 4 + t];
    }

    // ---- molecule index: fast uniform path, fallback scan ----
    int c0v = __ldg(&na[0]);
    bool uni = true;
    #pragma unroll
    for (int k = 0; k < 4; k++) {
        int idx = 4 * t + k;
        if (idx < M) uni &= (__ldg(&na[idx]) == c0v);
    }
    int allUni = __syncthreads_and((int)uni);       // also fences s_xyz

    int a = blockBase + t;
    int mol = 0;
    if (allUni) {
        float rc = 1.f / (float)c0v;
        mol = (int)(((float)((a < N) ? a : 0) + 0.5f) * rc);
        mol = min(mol, M - 1);
    } else {
        __shared__ int sp[1026];
        __shared__ int s_wsum[8];
        int lane = t & 31, warp = t >> 5;
        int v0 = (4 * t + 0 < M) ? __ldg(&na[4 * t + 0]) : 0;
        int v1 = (4 * t + 1 < M) ? __ldg(&na[4 * t + 1]) : 0;
        int v2 = (4 * t + 2 < M) ? __ldg(&na[4 * t + 2]) : 0;
        int v3 = (4 * t + 3 < M) ? __ldg(&na[4 * t + 3]) : 0;
        int mysum = v0 + v1 + v2 + v3;
        int sc = mysum;
        #pragma unroll
        for (int o = 1; o < 32; o <<= 1) {
            int x = __shfl_up_sync(0xffffffffu, sc, o);
            if (lane >= o) sc += x;
        }
        if (lane == 31) s_wsum[warp] = sc;
        __syncthreads();
        if (warp == 0 && lane < 8) {
            int ws = s_wsum[lane];
            #pragma unroll
            for (int o = 1; o < 8; o <<= 1) {
                int x = __shfl_up_sync(0xffu, ws, o);
                if (lane >= o) ws += x;
            }
            s_wsum[lane] = ws;
        }
        __syncthreads();
        int base_excl = sc - mysum + (warp > 0 ? s_wsum[warp - 1] : 0);
        sp[4 * t + 0] = base_excl;
        sp[4 * t + 1] = base_excl + v0;
        sp[4 * t + 2] = base_excl + v0 + v1;
        sp[4 * t + 3] = base_excl + v0 + v1 + v2;
        if (t == 0) { sp[1024] = 0x7fffffff; sp[1025] = 0x7fffffff; }
        __syncthreads();
        int lo = 0, hi = M;
        int key = (a < N) ? a : 0;
        while (hi - lo > 1) {
            int mid = (lo + hi) >> 1;
            if (sp[mid] <= key) lo = mid; else hi = mid;
        }
        mol = lo;
    }

    if (a >= N) return;
    float4 v;
    v.x = s_xyz[3 * t];
    v.y = s_xyz[3 * t + 1];
    v.z = s_xyz[3 * t + 2];
    v.w = __int_as_float((__ldg(&z[a]) & 255) | (mol << 8));
    g_atoms[a] = v;
}

// ---------------- main edge kernel: 4 edges/thread + fused final reduce ----
__global__ void __launch_bounds__(256)
k_edges(const int4* __restrict__ nb4, const float4* __restrict__ off4,
        const int2* __restrict__ nb, const float* __restrict__ off,
        float* __restrict__ out, int E, int M) {
    __shared__ float s_zpd[128];
    __shared__ int s_last;
    int t = threadIdx.x;
    if (t < 128) s_zpd[t] = g_zpd[t];
    __syncthreads();

    const float c0 = g_k[0], c1 = g_k[1], c2 = g_k[2], c3 = g_k[3];
    const float e0 = g_k[4], e1 = g_k[5], e2 = g_k[6], e3 = g_k[7];
    const int slot = t & 31;

    auto body = [&](int i, int j, float ox, float oy, float oz) {
        if (j <= i) return;
        float4 ai = g_atoms[i];
        float4 aj = g_atoms[j];
        float dx = ai.x - aj.x - ox;
        float dy = ai.y - aj.y - oy;
        float dz = ai.z - aj.z - oz;
        float d2 = fmaf(dx, dx, fmaf(dy, dy, dz * dz)) + 3e-15f;
        if (d2 >= 25.f) return;
        float rinv = rsqrtf(d2);
        float r    = d2 * rinv;
        int wi = __float_as_int(ai.w);
        int wj = __float_as_int(aj.w);
        float tt = -r * (s_zpd[wi & 255] + s_zpd[wj & 255]);
        float phi = fmaf(c0, __expf(e0 * tt),
                    fmaf(c1, __expf(e1 * tt),
                    fmaf(c2, __expf(e2 * tt),
                         c3 * __expf(e3 * tt))));
        float fcut = __expf(__fdividef(-d2, 25.f - d2));
        float zif = (float)(wi & 255);
        float zjf = (float)(wj & 255);
        float pair = zif * zjf * rinv * phi * fcut;
        atomicAdd(&g_acc[((wi >> 8) << 5) + slot], pair);
    };

    int gt = blockIdx.x * blockDim.x + t;
    int G = E >> 2;            // groups of 4 edges
    if (gt < G) {
        int4 n01 = nb4[2 * gt];
        int4 n23 = nb4[2 * gt + 1];
        float4 o0 = off4[3 * gt];
        float4 o1 = off4[3 * gt + 1];
        float4 o2 = off4[3 * gt + 2];
        body(n01.x, n01.y, o0.x, o0.y, o0.z);
        body(n01.z, n01.w, o0.w, o1.x, o1.y);
        body(n23.x, n23.y, o1.z, o1.w, o2.x);
        body(n23.z, n23.w, o2.y, o2.z, o2.w);
    }
    if (gt == 0) {             // tail edges
        for (int e = G * 4; e < E; e++) {
            int2 p = nb[e];
            body(p.x, p.y, off[3 * e], off[3 * e + 1], off[3 * e + 2]);
        }
    }

    // ---- fused final reduce: last block to arrive sums g_acc -> out ----
    __threadfence();                   // drain this block's atomics
    if (t == 0)
        s_last = (atomicAdd(&g_done, 1u) == gridDim.x - 1);
    __syncthreads();
    if (s_last) {
        for (int m = t; m < M; m += blockDim.x) {
            const float4* a4 = (const float4*)&g_acc[m << 5];
            float s = 0.f;
            #pragma unroll
            for (int k = 0; k < 8; k++) {
                float4 v = __ldcg(&a4[k]);
                s += v.x + v.y + v.z + v.w;
            }
            out[m] = s;
        }
    }
}

// ---------------- launch ----------------
extern "C" void kernel_launch(void* const* d_in, const int* in_sizes, int n_in,
                              void* d_out, int out_size) {
    const float* xyz    = (const float*)d_in[0];
    const int*   z      = (const int*)  d_in[1];
    const int*   nbrs   = (const int*)  d_in[2];
    const int*   natoms = (const int*)  d_in[3];
    const float* off    = (const float*)d_in[4];
    const float* d_inv  = (const float*)d_in[5];
    const float* ze_inv = (const float*)d_in[6];
    const float* c_inv  = (const float*)d_in[7];
    const float* ex_inv = (const float*)d_in[8];

    int N = in_sizes[1];
    int E = in_sizes[2] / 2;
    int M = in_sizes[3];
    float* out = (float*)d_out;

    k_atoms<<<(N + 255) / 256, 256>>>(xyz, z, natoms,
                                      d_inv, ze_inv, c_inv, ex_inv, N, M);
    int G = E / 4;
    k_edges<<<(G + 255) / 256, 256>>>((const int4*)nbrs, (const float4*)off,
                                      (const int2*)nbrs, off, out, E, M);
}

// round 16
// speedup vs baseline: 1.2654x; 1.2654x over previous
#include <cuda_runtime.h>
#include <math.h>

#define KE_KCAL 332.0636f

// ---------------- scratch (no allocations allowed) ----------------
// NOTE: __device__ globals are zero-initialized at module load; g_acc's
// zero-invariant is re-established by k_reduce after each read.
__device__ float4 g_atoms[262144];    // packed per-atom: x,y,z, (z | mol<<8)
__device__ float  g_acc[1024 * 32];   // padded per-molecule accumulators
__device__ float  g_zpd[128];         // z^z_exp / d
__device__ float  g_k[8];             // c'_k = c_k*KE/csum ; e_k

// ---------------- atom packing + consts (R8 minus acc zeroing) ----------
__global__ void __launch_bounds__(256)
k_atoms(const float* __restrict__ xyz,
        const int*   __restrict__ z,
        const int*   __restrict__ na,
        const float* __restrict__ d_inv,  const float* __restrict__ ze_inv,
        const float* __restrict__ c_inv,  const float* __restrict__ ex_inv,
        int N, int M) {
    __shared__ float s_xyz[768];      // 256 atoms * 3 floats, staged coalesced
    int t = threadIdx.x;

    // block 0: compute softplus consts + zpd table once
    if (blockIdx.x == 0) {
        if (t < 4)       g_k[t + 4] = log1pf(expf(__ldg(&ex_inv[t])));
        else if (t == 4) {
            float csum = 0.f, cc[4];
            #pragma unroll
            for (int k = 0; k < 4; k++) {
                cc[k] = log1pf(expf(__ldg(&c_inv[k])));
                csum += cc[k];
            }
            float s = KE_KCAL / csum;
            #pragma unroll
            for (int k = 0; k < 4; k++) g_k[k] = cc[k] * s;
        }
        if (t >= 32 && t < 160) {
            int zz = t - 32;
            float ze = log1pf(expf(__ldg(&ze_inv[0])));
            float dinv = 1.f / log1pf(expf(__ldg(&d_inv[0])));
            g_zpd[zz] = (zz == 0) ? 0.f : powf((float)zz, ze) * dinv;
        }
    }

    // ---- stage this block's xyz chunk through shared (coalesced float4) ----
    int blockBase = blockIdx.x * blockDim.x;
    int nAtoms = min(256, N - blockBase);
    if (nAtoms <= 0) return;
    {
        int nFloats = nAtoms * 3;
        int nVec = nFloats >> 2;
        const float4* src = (const float4*)(xyz + blockBase * 3);
        if (t < nVec) ((float4*)s_xyz)[t] = src[t];
        int rem = nFloats - nVec * 4;
        if (t < rem) s_xyz[nVec * 4 + t] = xyz[blockBase * 3 + nVec * 4 + t];
    }

    // ---- molecule index: fast uniform path, fallback scan ----
    int c0v = __ldg(&na[0]);
    bool uni = true;
    #pragma unroll
    for (int k = 0; k < 4; k++) {
        int idx = 4 * t + k;
        if (idx < M) uni &= (__ldg(&na[idx]) == c0v);
    }
    int allUni = __syncthreads_and((int)uni);       // also fences s_xyz

    int a = blockBase + t;
    int mol = 0;
    if (allUni) {
        float rc = 1.f / (float)c0v;
        mol = (int)(((float)((a < N) ? a : 0) + 0.5f) * rc);
        mol = min(mol, M - 1);
    } else {
        __shared__ int sp[1026];
        __shared__ int s_wsum[8];
        int lane = t & 31, warp = t >> 5;
        int v0 = (4 * t + 0 < M) ? __ldg(&na[4 * t + 0]) : 0;
        int v1 = (4 * t + 1 < M) ? __ldg(&na[4 * t + 1]) : 0;
        int v2 = (4 * t + 2 < M) ? __ldg(&na[4 * t + 2]) : 0;
        int v3 = (4 * t + 3 < M) ? __ldg(&na[4 * t + 3]) : 0;
        int mysum = v0 + v1 + v2 + v3;
        int sc = mysum;
        #pragma unroll
        for (int o = 1; o < 32; o <<= 1) {
            int x = __shfl_up_sync(0xffffffffu, sc, o);
            if (lane >= o) sc += x;
        }
        if (lane == 31) s_wsum[warp] = sc;
        __syncthreads();
        if (warp == 0 && lane < 8) {
            int ws = s_wsum[lane];
            #pragma unroll
            for (int o = 1; o < 8; o <<= 1) {
                int x = __shfl_up_sync(0xffu, ws, o);
                if (lane >= o) ws += x;
            }
            s_wsum[lane] = ws;
        }
        __syncthreads();
        int base_excl = sc - mysum + (warp > 0 ? s_wsum[warp - 1] : 0);
        sp[4 * t + 0] = base_excl;
        sp[4 * t + 1] = base_excl + v0;
        sp[4 * t + 2] = base_excl + v0 + v1;
        sp[4 * t + 3] = base_excl + v0 + v1 + v2;
        if (t == 0) { sp[1024] = 0x7fffffff; sp[1025] = 0x7fffffff; }
        __syncthreads();
        int lo = 0, hi = M;
        int key = (a < N) ? a : 0;
        while (hi - lo > 1) {
            int mid = (lo + hi) >> 1;
            if (sp[mid] <= key) lo = mid; else hi = mid;
        }
        mol = lo;
    }

    if (a >= N) return;
    float4 v;
    v.x = s_xyz[3 * t];
    v.y = s_xyz[3 * t + 1];
    v.z = s_xyz[3 * t + 2];
    v.w = __int_as_float((__ldg(&z[a]) & 255) | (mol << 8));
    g_atoms[a] = v;
}

// ---------------- main edge kernel: 4 edges/thread, flat 256 (R8 frozen) ---
__global__ void __launch_bounds__(256)
k_edges(const int4* __restrict__ nb4, const float4* __restrict__ off4,
        const int2* __restrict__ nb, const float* __restrict__ off, int E) {
    __shared__ float s_zpd[128];
    int t = threadIdx.x;
    if (t < 128) s_zpd[t] = g_zpd[t];
    __syncthreads();

    const float c0 = g_k[0], c1 = g_k[1], c2 = g_k[2], c3 = g_k[3];
    const float e0 = g_k[4], e1 = g_k[5], e2 = g_k[6], e3 = g_k[7];
    const int slot = t & 31;

    auto body = [&](int i, int j, float ox, float oy, float oz) {
        if (j <= i) return;
        float4 ai = g_atoms[i];
        float4 aj = g_atoms[j];
        float dx = ai.x - aj.x - ox;
        float dy = ai.y - aj.y - oy;
        float dz = ai.z - aj.z - oz;
        float d2 = fmaf(dx, dx, fmaf(dy, dy, dz * dz)) + 3e-15f;
        if (d2 >= 25.f) return;
        float rinv = rsqrtf(d2);
        float r    = d2 * rinv;
        int wi = __float_as_int(ai.w);
        int wj = __float_as_int(aj.w);
        float tt = -r * (s_zpd[wi & 255] + s_zpd[wj & 255]);
        float phi = fmaf(c0, __expf(e0 * tt),
                    fmaf(c1, __expf(e1 * tt),
                    fmaf(c2, __expf(e2 * tt),
                         c3 * __expf(e3 * tt))));
        float fcut = __expf(__fdividef(-d2, 25.f - d2));
        float zif = (float)(wi & 255);
        float zjf = (float)(wj & 255);
        float pair = zif * zjf * rinv * phi * fcut;
        atomicAdd(&g_acc[((wi >> 8) << 5) + slot], pair);
    };

    int gt = blockIdx.x * blockDim.x + t;
    int G = E >> 2;            // groups of 4 edges
    if (gt < G) {
        int4 n01 = nb4[2 * gt];
        int4 n23 = nb4[2 * gt + 1];
        float4 o0 = off4[3 * gt];
        float4 o1 = off4[3 * gt + 1];
        float4 o2 = off4[3 * gt + 2];
        body(n01.x, n01.y, o0.x, o0.y, o0.z);
        body(n01.z, n01.w, o0.w, o1.x, o1.y);
        body(n23.x, n23.y, o1.z, o1.w, o2.x);
        body(n23.z, n23.w, o2.y, o2.z, o2.w);
    }
    if (gt == 0) {             // tail edges
        for (int e = G * 4; e < E; e++) {
            int2 p = nb[e];
            body(p.x, p.y, off[3 * e], off[3 * e + 1], off[3 * e + 2]);
        }
    }
}

// ---------------- final reduce: one warp per molecule; re-zero g_acc -------
__global__ void __launch_bounds__(256)
k_reduce(float* __restrict__ out, int M) {
    int gt = blockIdx.x * blockDim.x + threadIdx.x;
    int m = gt >> 5, lane = gt & 31;
    if (m >= M) return;
    float* slotp = &g_acc[(m << 5) + lane];
    float v = *slotp;
    *slotp = 0.f;                     // re-establish zero-invariant for replay
    #pragma unroll
    for (int o = 16; o > 0; o >>= 1)
        v += __shfl_down_sync(0xffffffffu, v, o);
    if (lane == 0) out[m] = v;
}

// ---------------- launch ----------------
extern "C" void kernel_launch(void* const* d_in, const int* in_sizes, int n_in,
                              void* d_out, int out_size) {
    const float* xyz    = (const float*)d_in[0];
    const int*   z      = (const int*)  d_in[1];
    const int*   nbrs   = (const int*)  d_in[2];
    const int*   natoms = (const int*)  d_in[3];
    const float* off    = (const float*)d_in[4];
    const float* d_inv  = (const float*)d_in[5];
    const float* ze_inv = (const float*)d_in[6];
    const float* c_inv  = (const float*)d_in[7];
    const float* ex_inv = (const float*)d_in[8];

    int N = in_sizes[1];
    int E = in_sizes[2] / 2;
    int M = in_sizes[3];
    float* out = (float*)d_out;

    k_atoms<<<(N + 255) / 256, 256>>>(xyz, z, natoms,
                                      d_inv, ze_inv, c_inv, ex_inv, N, M);
    int G = E / 4;
    k_edges<<<(G + 255) / 256, 256>>>((const int4*)nbrs, (const float4*)off,
                                      (const int2*)nbrs, off, E);
    k_reduce<<<(M * 32 + 255) / 256, 256>>>(out, M);
}

// round 17
// speedup vs baseline: 1.3053x; 1.0315x over previous
#include <cuda_runtime.h>
#include <math.h>

#define KE_KCAL 332.0636f

// ---------------- scratch (no allocations allowed) ----------------
__device__ float4 g_atoms[262144];    // packed per-atom: x,y,z, (z | mol<<8)
__device__ float  g_acc[1024 * 32];   // padded per-molecule accumulators
__device__ float  g_zpd[128];         // z^z_exp / d
__device__ float  g_k[8];             // c'_k = c_k*KE/csum ; e_k

// ---------------- atom packing + consts + acc zero (R8, 57.9us measured) ---
__global__ void __launch_bounds__(256)
k_atoms(const float* __restrict__ xyz,
        const int*   __restrict__ z,
        const int*   __restrict__ na,
        const float* __restrict__ d_inv,  const float* __restrict__ ze_inv,
        const float* __restrict__ c_inv,  const float* __restrict__ ex_inv,
        int N, int M) {
    __shared__ float s_xyz[768];      // 256 atoms * 3 floats, staged coalesced
    int t = threadIdx.x;
    int gtid = blockIdx.x * blockDim.x + t;

    // block 0: compute softplus consts + zpd table once
    if (blockIdx.x == 0) {
        if (t < 4)       g_k[t + 4] = log1pf(expf(__ldg(&ex_inv[t])));
        else if (t == 4) {
            float csum = 0.f, cc[4];
            #pragma unroll
            for (int k = 0; k < 4; k++) {
                cc[k] = log1pf(expf(__ldg(&c_inv[k])));
                csum += cc[k];
            }
            float s = KE_KCAL / csum;
            #pragma unroll
            for (int k = 0; k < 4; k++) g_k[k] = cc[k] * s;
        }
        if (t >= 32 && t < 160) {
            int zz = t - 32;
            float ze = log1pf(expf(__ldg(&ze_inv[0])));
            float dinv = 1.f / log1pf(expf(__ldg(&d_inv[0])));
            g_zpd[zz] = (zz == 0) ? 0.f : powf((float)zz, ze) * dinv;
        }
    }

    // zero accumulators
    if (gtid < 2048) {
        float4 zv = make_float4(0.f, 0.f, 0.f, 0.f);
        #pragma unroll
        for (int k = 0; k < 4; k++)
            ((float4*)g_acc)[gtid + k * 2048] = zv;
    }

    // ---- stage this block's xyz chunk through shared (coalesced float4) ----
    int blockBase = blockIdx.x * blockDim.x;
    int nAtoms = min(256, N - blockBase);
    if (nAtoms <= 0) return;
    {
        int nFloats = nAtoms * 3;
        int nVec = nFloats >> 2;
        const float4* src = (const float4*)(xyz + blockBase * 3);
        if (t < nVec) ((float4*)s_xyz)[t] = src[t];
        int rem = nFloats - nVec * 4;
        if (t < rem) s_xyz[nVec * 4 + t] = xyz[blockBase * 3 + nVec * 4 + t];
    }

    // ---- molecule index: fast uniform path, fallback scan ----
    int c0v = __ldg(&na[0]);
    bool uni = true;
    #pragma unroll
    for (int k = 0; k < 4; k++) {
        int idx = 4 * t + k;
        if (idx < M) uni &= (__ldg(&na[idx]) == c0v);
    }
    int allUni = __syncthreads_and((int)uni);       // also fences s_xyz

    int a = blockBase + t;
    int mol = 0;
    if (allUni) {
        float rc = 1.f / (float)c0v;
        mol = (int)(((float)((a < N) ? a : 0) + 0.5f) * rc);
        mol = min(mol, M - 1);
    } else {
        __shared__ int sp[1026];
        __shared__ int s_wsum[8];
        int lane = t & 31, warp = t >> 5;
        int v0 = (4 * t + 0 < M) ? __ldg(&na[4 * t + 0]) : 0;
        int v1 = (4 * t + 1 < M) ? __ldg(&na[4 * t + 1]) : 0;
        int v2 = (4 * t + 2 < M) ? __ldg(&na[4 * t + 2]) : 0;
        int v3 = (4 * t + 3 < M) ? __ldg(&na[4 * t + 3]) : 0;
        int mysum = v0 + v1 + v2 + v3;
        int sc = mysum;
        #pragma unroll
        for (int o = 1; o < 32; o <<= 1) {
            int x = __shfl_up_sync(0xffffffffu, sc, o);
            if (lane >= o) sc += x;
        }
        if (lane == 31) s_wsum[warp] = sc;
        __syncthreads();
        if (warp == 0 && lane < 8) {
            int ws = s_wsum[lane];
            #pragma unroll
            for (int o = 1; o < 8; o <<= 1) {
                int x = __shfl_up_sync(0xffu, ws, o);
                if (lane >= o) ws += x;
            }
            s_wsum[lane] = ws;
        }
        __syncthreads();
        int base_excl = sc - mysum + (warp > 0 ? s_wsum[warp - 1] : 0);
        sp[4 * t + 0] = base_excl;
        sp[4 * t + 1] = base_excl + v0;
        sp[4 * t + 2] = base_excl + v0 + v1;
        sp[4 * t + 3] = base_excl + v0 + v1 + v2;
        if (t == 0) { sp[1024] = 0x7fffffff; sp[1025] = 0x7fffffff; }
        __syncthreads();
        int lo = 0, hi = M;
        int key = (a < N) ? a : 0;
        while (hi - lo > 1) {
            int mid = (lo + hi) >> 1;
            if (sp[mid] <= key) lo = mid; else hi = mid;
        }
        mol = lo;
    }

    if (a >= N) return;
    float4 v;
    v.x = s_xyz[3 * t];
    v.y = s_xyz[3 * t + 1];
    v.z = s_xyz[3 * t + 2];
    v.w = __int_as_float((__ldg(&z[a]) & 255) | (mol << 8));
    g_atoms[a] = v;
}

// ---------------- main edge kernel: 4 edges/thread, flat 256 (frozen) ------
__global__ void __launch_bounds__(256)
k_edges(const int4* __restrict__ nb4, const float4* __restrict__ off4,
        const int2* __restrict__ nb, const float* __restrict__ off, int E) {
    __shared__ float s_zpd[128];
    int t = threadIdx.x;
    if (t < 128) s_zpd[t] = g_zpd[t];
    __syncthreads();

    const float c0 = g_k[0], c1 = g_k[1], c2 = g_k[2], c3 = g_k[3];
    const float e0 = g_k[4], e1 = g_k[5], e2 = g_k[6], e3 = g_k[7];
    const int slot = t & 31;

    auto body = [&](int i, int j, float ox, float oy, float oz) {
        if (j <= i) return;
        float4 ai = g_atoms[i];
        float4 aj = g_atoms[j];
        float dx = ai.x - aj.x - ox;
        float dy = ai.y - aj.y - oy;
        float dz = ai.z - aj.z - oz;
        float d2 = fmaf(dx, dx, fmaf(dy, dy, dz * dz)) + 3e-15f;
        if (d2 >= 25.f) return;
        float rinv = rsqrtf(d2);
        float r    = d2 * rinv;
        int wi = __float_as_int(ai.w);
        int wj = __float_as_int(aj.w);
        float tt = -r * (s_zpd[wi & 255] + s_zpd[wj & 255]);
        float phi = fmaf(c0, __expf(e0 * tt),
                    fmaf(c1, __expf(e1 * tt),
                    fmaf(c2, __expf(e2 * tt),
                         c3 * __expf(e3 * tt))));
        float fcut = __expf(__fdividef(-d2, 25.f - d2));
        float zif = (float)(wi & 255);
        float zjf = (float)(wj & 255);
        float pair = zif * zjf * rinv * phi * fcut;
        atomicAdd(&g_acc[((wi >> 8) << 5) + slot], pair);
    };

    int gt = blockIdx.x * blockDim.x + t;
    int G = E >> 2;            // groups of 4 edges
    if (gt < G) {
        int4 n01 = nb4[2 * gt];
        int4 n23 = nb4[2 * gt + 1];
        float4 o0 = off4[3 * gt];
        float4 o1 = off4[3 * gt + 1];
        float4 o2 = off4[3 * gt + 2];
        body(n01.x, n01.y, o0.x, o0.y, o0.z);
        body(n01.z, n01.w, o0.w, o1.x, o1.y);
        body(n23.x, n23.y, o1.z, o1.w, o2.x);
        body(n23.z, n23.w, o2.y, o2.z, o2.w);
    }
    if (gt == 0) {             // tail edges
        for (int e = G * 4; e < E; e++) {
            int2 p = nb[e];
            body(p.x, p.y, off[3 * e], off[3 * e + 1], off[3 * e + 2]);
        }
    }
}

// ---------------- final reduce: one warp per molecule ----------------
__global__ void __launch_bounds__(256)
k_reduce(float* __restrict__ out, int M) {
    int gt = blockIdx.x * blockDim.x + threadIdx.x;
    int m = gt >> 5, lane = gt & 31;
    if (m >= M) return;
    float v = g_acc[(m << 5) + lane];
    #pragma unroll
    for (int o = 16; o > 0; o >>= 1)
        v += __shfl_down_sync(0xffffffffu, v, o);
    if (lane == 0) out[m] = v;
}

// ---------------- launch ----------------
extern "C" void kernel_launch(void* const* d_in, const int* in_sizes, int n_in,
                              void* d_out, int out_size) {
    const float* xyz    = (const float*)d_in[0];
    const int*   z      = (const int*)  d_in[1];
    const int*   nbrs   = (const int*)  d_in[2];
    const int*   natoms = (const int*)  d_in[3];
    const float* off    = (const float*)d_in[4];
    const float* d_inv  = (const float*)d_in[5];
    const float* ze_inv = (const float*)d_in[6];
    const float* c_inv  = (const float*)d_in[7];
    const float* ex_inv = (const float*)d_in[8];

    int N = in_sizes[1];
    int E = in_sizes[2] / 2;
    int M = in_sizes[3];
    float* out = (float*)d_out;

    k_atoms<<<(N + 255) / 256, 256>>>(xyz, z, natoms,
                                      d_inv, ze_inv, c_inv, ex_inv, N, M);
    int G = E / 4;
    k_edges<<<(G + 255) / 256, 256>>>((const int4*)nbrs, (const float4*)off,
                                      (const int2*)nbrs, off, E);
    k_reduce<<<(M * 32 + 255) / 256, 256>>>(out, M);
}